// round 2
// baseline (speedup 1.0000x reference)
#include <cuda_runtime.h>

#define Nn   20000
#define Ee   320000
#define DIN  128
#define Hh   512
#define NOUT 7
#define TOT  (Ee + Nn)
#define EPSL 1e-5f

// ---- scratch (no allocs allowed: __device__ globals) ----
__device__ float g_h[(size_t)Nn * Hh];    // GEMM output (pre-aggregation)
__device__ float g_x[(size_t)Nn * Hh];    // layer activations
__device__ float g_deg[Nn];
__device__ float g_dinv[Nn];
__device__ int   g_off[Nn + 1];
__device__ int   g_cur[Nn];
__device__ int   g_srcv[TOT];
__device__ float g_wv[TOT];
__device__ float g_pool[Hh];

// ---------------- graph preprocessing ----------------

__global__ void init_kernel() {
    int i = blockIdx.x * blockDim.x + threadIdx.x;
    if (i < Nn) { g_deg[i] = 0.f; g_cur[i] = 0; }
    if (i < Hh) g_pool[i] = 0.f;
}

__global__ void deg_kernel(const int* __restrict__ ei) {
    int i = blockIdx.x * blockDim.x + threadIdx.x;
    if (i < Ee) {
        int d = ei[Ee + i];                 // dst row (int32!)
        atomicAdd(&g_deg[d], 1.0f);
    }
}

__global__ void dinv_kernel() {
    int i = blockIdx.x * blockDim.x + threadIdx.x;
    if (i < Nn) {
        float d = g_deg[i] + 1.0f;   // + self loop
        g_dinv[i] = rsqrtf(d);
    }
}

// single-block Hillis-Steele scan over 20000 degrees -> exclusive offsets
__global__ void scan_kernel() {
    __shared__ int sh[1024];
    __shared__ int carry;
    int t = threadIdx.x;
    if (t == 0) { carry = 0; g_off[0] = 0; }
    __syncthreads();
    for (int base = 0; base < Nn; base += 1024) {
        int i = base + t;
        int v = (i < Nn) ? ((int)g_deg[i] + 1) : 0;
        sh[t] = v;
        __syncthreads();
        for (int off = 1; off < 1024; off <<= 1) {
            int tmp = 0;
            if (t >= off) tmp = sh[t - off];
            __syncthreads();
            if (t >= off) sh[t] += tmp;
            __syncthreads();
        }
        if (i < Nn) g_off[i + 1] = carry + sh[t];
        __syncthreads();
        if (t == 0) carry += sh[1023];
        __syncthreads();
    }
}

__global__ void fill_kernel(const int* __restrict__ ei) {
    int i = blockIdx.x * blockDim.x + threadIdx.x;
    if (i >= TOT) return;
    int s, d;
    if (i < Ee) { s = ei[i]; d = ei[Ee + i]; }
    else        { s = i - Ee; d = s; }               // self loop
    int pos = atomicAdd(&g_cur[d], 1);
    int idx = g_off[d] + pos;
    g_srcv[idx] = s;
    g_wv[idx]   = g_dinv[s] * g_dinv[d];
}

// ---------------- dense GEMM: C[N,512] = A[N,K] @ W[K,512] ----------------
// 128x128 block tile, BK=8, 256 threads, 8x8 microtile, double-buffered smem.

__global__ void __launch_bounds__(256, 2)
gemm_kernel(const float* __restrict__ Aq, const float* __restrict__ B, int K) {
    __shared__ __align__(16) float As[2][8][128];
    __shared__ __align__(16) float Bs[2][8][128];

    const float* A = Aq ? Aq : g_x;
    float* C = g_h;

    const int tid  = threadIdx.x;
    const int m0   = blockIdx.y * 128;
    const int n0   = blockIdx.x * 128;
    const int arow = tid >> 1;
    const int acol = (tid & 1) * 4;
    const int brow = tid >> 5;
    const int bcol = (tid & 31) * 4;
    const int lane = tid & 31;
    const int w    = tid >> 5;
    const int wr = w >> 1, wc = w & 1;
    const int lr = lane >> 3, lc = lane & 7;
    const int aoff = wr * 32 + lr * 8;   // row offset within tile
    const int boff = wc * 64 + lc * 8;   // col offset within tile

    float acc[8][8];
#pragma unroll
    for (int i = 0; i < 8; i++)
#pragma unroll
        for (int j = 0; j < 8; j++) acc[i][j] = 0.f;

    const int KT = K >> 3;

    // prologue: load tile 0
    {
        int row = m0 + arow;
        float4 av = make_float4(0.f, 0.f, 0.f, 0.f);
        if (row < Nn) av = *(const float4*)&A[(size_t)row * K + acol];
        As[0][acol + 0][arow] = av.x;
        As[0][acol + 1][arow] = av.y;
        As[0][acol + 2][arow] = av.z;
        As[0][acol + 3][arow] = av.w;
        float4 bv = *(const float4*)&B[(size_t)brow * Hh + n0 + bcol];
        *(float4*)&Bs[0][brow][bcol] = bv;
    }
    __syncthreads();

    for (int kt = 0; kt < KT; kt++) {
        int cur = kt & 1;
        if (kt + 1 < KT) {
            int nb = cur ^ 1;
            int k0 = (kt + 1) * 8;
            int row = m0 + arow;
            float4 av = make_float4(0.f, 0.f, 0.f, 0.f);
            if (row < Nn) av = *(const float4*)&A[(size_t)row * K + k0 + acol];
            As[nb][acol + 0][arow] = av.x;
            As[nb][acol + 1][arow] = av.y;
            As[nb][acol + 2][arow] = av.z;
            As[nb][acol + 3][arow] = av.w;
            float4 bv = *(const float4*)&B[(size_t)(k0 + brow) * Hh + n0 + bcol];
            *(float4*)&Bs[nb][brow][bcol] = bv;
        }
#pragma unroll
        for (int k = 0; k < 8; k++) {
            float4 a0 = *(const float4*)&As[cur][k][aoff];
            float4 a1 = *(const float4*)&As[cur][k][aoff + 4];
            float4 b0 = *(const float4*)&Bs[cur][k][boff];
            float4 b1 = *(const float4*)&Bs[cur][k][boff + 4];
            float ar[8] = {a0.x, a0.y, a0.z, a0.w, a1.x, a1.y, a1.z, a1.w};
            float br[8] = {b0.x, b0.y, b0.z, b0.w, b1.x, b1.y, b1.z, b1.w};
#pragma unroll
            for (int i = 0; i < 8; i++)
#pragma unroll
                for (int j = 0; j < 8; j++)
                    acc[i][j] = fmaf(ar[i], br[j], acc[i][j]);
        }
        __syncthreads();
    }

#pragma unroll
    for (int i = 0; i < 8; i++) {
        int row = m0 + aoff + i;
        if (row < Nn) {
            float4 v0 = make_float4(acc[i][0], acc[i][1], acc[i][2], acc[i][3]);
            float4 v1 = make_float4(acc[i][4], acc[i][5], acc[i][6], acc[i][7]);
            *(float4*)&C[(size_t)row * Hh + n0 + boff]     = v0;
            *(float4*)&C[(size_t)row * Hh + n0 + boff + 4] = v1;
        }
    }
}

// ------- fused CSR gather-aggregate + bias + LayerNorm + ReLU -------
// one block per node; 128 threads x float4 covers H=512

__global__ void __launch_bounds__(128)
agg_kernel(const float* __restrict__ bias,
           const float* __restrict__ gamma,
           const float* __restrict__ beta) {
    const int n = blockIdx.x;
    const int t = threadIdx.x;
    const int beg = g_off[n], end = g_off[n + 1];
    const int fo = t * 4;

    float4 acc = make_float4(0.f, 0.f, 0.f, 0.f);
    for (int j = beg; j < end; j++) {
        int   s = g_srcv[j];
        float wv = g_wv[j];
        float4 v = *(const float4*)&g_h[(size_t)s * Hh + fo];
        acc.x = fmaf(wv, v.x, acc.x);
        acc.y = fmaf(wv, v.y, acc.y);
        acc.z = fmaf(wv, v.z, acc.z);
        acc.w = fmaf(wv, v.w, acc.w);
    }
    float4 b = *(const float4*)&bias[fo];
    acc.x += b.x; acc.y += b.y; acc.z += b.z; acc.w += b.w;

    float s1 = acc.x + acc.y + acc.z + acc.w;
    float s2 = acc.x * acc.x + acc.y * acc.y + acc.z * acc.z + acc.w * acc.w;
#pragma unroll
    for (int o = 16; o > 0; o >>= 1) {
        s1 += __shfl_xor_sync(0xffffffffu, s1, o);
        s2 += __shfl_xor_sync(0xffffffffu, s2, o);
    }
    __shared__ float sm1[4], sm2[4];
    if ((t & 31) == 0) { sm1[t >> 5] = s1; sm2[t >> 5] = s2; }
    __syncthreads();
    float S1 = sm1[0] + sm1[1] + sm1[2] + sm1[3];
    float S2 = sm2[0] + sm2[1] + sm2[2] + sm2[3];
    float mu  = S1 * (1.0f / Hh);
    float var = S2 * (1.0f / Hh) - mu * mu;
    float inv = rsqrtf(var + EPSL);

    float4 gm = *(const float4*)&gamma[fo];
    float4 bt = *(const float4*)&beta[fo];
    float4 y;
    y.x = fmaxf((acc.x - mu) * inv * gm.x + bt.x, 0.f);
    y.y = fmaxf((acc.y - mu) * inv * gm.y + bt.y, 0.f);
    y.z = fmaxf((acc.z - mu) * inv * gm.z + bt.z, 0.f);
    y.w = fmaxf((acc.w - mu) * inv * gm.w + bt.w, 0.f);
    *(float4*)&g_x[(size_t)n * Hh + fo] = y;
}

// ---------------- mean pool + output projection ----------------

__global__ void pool_kernel() {
    int f = threadIdx.x;   // 512 threads
    float s = 0.f;
    for (int n = blockIdx.x; n < Nn; n += gridDim.x)
        s += g_x[(size_t)n * Hh + f];
    atomicAdd(&g_pool[f], s);
}

__global__ void out_kernel(const float* __restrict__ Wout,
                           const float* __restrict__ bout,
                           float* __restrict__ out) {
    __shared__ float sm[NOUT][256];
    int t = threadIdx.x;
    float acc[NOUT];
#pragma unroll
    for (int o = 0; o < NOUT; o++) acc[o] = 0.f;
    for (int f = t; f < Hh; f += 256) {
        float p = g_pool[f] * (1.0f / Nn);
#pragma unroll
        for (int o = 0; o < NOUT; o++)
            acc[o] = fmaf(p, Wout[f * NOUT + o], acc[o]);
    }
#pragma unroll
    for (int o = 0; o < NOUT; o++) sm[o][t] = acc[o];
    __syncthreads();
    for (int st = 128; st > 0; st >>= 1) {
        if (t < st) {
#pragma unroll
            for (int o = 0; o < NOUT; o++) sm[o][t] += sm[o][t + st];
        }
        __syncthreads();
    }
    if (t < NOUT) out[t] = sm[t][0] + bout[t];
}

// ---------------- launch ----------------

extern "C" void kernel_launch(void* const* d_in, const int* in_sizes, int n_in,
                              void* d_out, int out_size) {
    const float* x  = (const float*)d_in[0];
    const int*   ei = (const int*)d_in[1];     // int32! (JAX x64 disabled)
    const float* W1 = (const float*)d_in[2];  const float* b1 = (const float*)d_in[3];
    const float* W2 = (const float*)d_in[4];  const float* b2 = (const float*)d_in[5];
    const float* W3 = (const float*)d_in[6];  const float* b3 = (const float*)d_in[7];
    const float* W4 = (const float*)d_in[8];  const float* b4 = (const float*)d_in[9];
    const float* gm = (const float*)d_in[10]; const float* bt = (const float*)d_in[11];
    const float* Wo = (const float*)d_in[12]; const float* bo = (const float*)d_in[13];
    float* out = (float*)d_out;

    init_kernel<<<(Nn + 255) / 256, 256>>>();
    deg_kernel<<<(Ee + 255) / 256, 256>>>(ei);
    dinv_kernel<<<(Nn + 255) / 256, 256>>>();
    scan_kernel<<<1, 1024>>>();
    fill_kernel<<<(TOT + 255) / 256, 256>>>(ei);

    dim3 ggrid(Hh / 128, (Nn + 127) / 128);

    // layer 1 (K = 128, input = x)
    gemm_kernel<<<ggrid, 256>>>(x, W1, DIN);
    agg_kernel<<<Nn, 128>>>(b1, gm, bt);
    // layer 2
    gemm_kernel<<<ggrid, 256>>>(nullptr, W2, Hh);
    agg_kernel<<<Nn, 128>>>(b2, gm, bt);
    // layer 3
    gemm_kernel<<<ggrid, 256>>>(nullptr, W3, Hh);
    agg_kernel<<<Nn, 128>>>(b3, gm, bt);
    // layer 4
    gemm_kernel<<<ggrid, 256>>>(nullptr, W4, Hh);
    agg_kernel<<<Nn, 128>>>(b4, gm, bt);

    pool_kernel<<<148, 512>>>();
    out_kernel<<<1, 256>>>(Wo, bo, out);
}

// round 6
// speedup vs baseline: 1.9813x; 1.9813x over previous
#include <cuda_runtime.h>
#include <cuda_bf16.h>
#include <cstdint>

#define Nn   20000
#define Ee   320000
#define DIN  128
#define Hh   512
#define NOUT 7
#define TOT  (Ee + Nn)
#define EPSL 1e-5f

// Wt layout: layer1 [512][128] then layers 2-4 [512][512] (hi and lo arrays)
#define WOFF1 0
#define WOFF2 65536
#define WOFF3 327680
#define WOFF4 589824
#define WTOT  851968

// ---- scratch (no allocs allowed: __device__ globals) ----
__device__ float g_h[(size_t)Nn * Hh];
__device__ float g_x[(size_t)Nn * Hh];
__device__ float g_deg[Nn];
__device__ float g_dinv[Nn];
__device__ int   g_off[Nn + 1];
__device__ int   g_cur[Nn];
__device__ int   g_srcv[TOT];
__device__ float g_wv[TOT];
__device__ float g_pool[Hh];
__device__ __nv_bfloat16 g_wt_hi[WTOT];
__device__ __nv_bfloat16 g_wt_lo[WTOT];

// ================= helpers =================

__device__ __forceinline__ uint32_t smem_u32(const void* p) {
    uint32_t a;
    asm("{ .reg .u64 t; cvta.to.shared.u64 t, %1; cvt.u32.u64 %0, t; }" : "=r"(a) : "l"(p));
    return a;
}
__device__ __forceinline__ void ldsm_x4(uint32_t* r, uint32_t addr) {
    asm volatile("ldmatrix.sync.aligned.m8n8.x4.shared.b16 {%0,%1,%2,%3}, [%4];"
                 : "=r"(r[0]), "=r"(r[1]), "=r"(r[2]), "=r"(r[3]) : "r"(addr));
}
__device__ __forceinline__ void mma16816(float* d, const uint32_t* a, const uint32_t* b) {
    asm volatile("mma.sync.aligned.m16n8k16.row.col.f32.bf16.bf16.f32 "
                 "{%0,%1,%2,%3}, {%4,%5,%6,%7}, {%8,%9}, {%0,%1,%2,%3};"
                 : "+f"(d[0]), "+f"(d[1]), "+f"(d[2]), "+f"(d[3])
                 : "r"(a[0]), "r"(a[1]), "r"(a[2]), "r"(a[3]), "r"(b[0]), "r"(b[1]));
}

static __device__ __forceinline__ void split2(float a, float b, unsigned& h, unsigned& l) {
    __nv_bfloat162 hh = __floats2bfloat162_rn(a, b);
    float ra = a - __bfloat162float(hh.x);
    float rb = b - __bfloat162float(hh.y);
    __nv_bfloat162 ll = __floats2bfloat162_rn(ra, rb);
    h = *(unsigned*)&hh;
    l = *(unsigned*)&ll;
}

// ================= graph preprocessing =================

__global__ void init_kernel() {
    int i = blockIdx.x * blockDim.x + threadIdx.x;
    if (i < Nn) { g_deg[i] = 0.f; g_cur[i] = 0; }
    if (i < Hh) g_pool[i] = 0.f;
}

__global__ void deg_kernel(const int* __restrict__ ei) {
    int i = blockIdx.x * blockDim.x + threadIdx.x;
    if (i < Ee) atomicAdd(&g_deg[ei[Ee + i]], 1.0f);
}

__global__ void dinv_kernel() {
    int i = blockIdx.x * blockDim.x + threadIdx.x;
    if (i < Nn) g_dinv[i] = rsqrtf(g_deg[i] + 1.0f);
}

// warp-shuffle based scan, 1024 threads, carry across 1024-chunks
__global__ void scan_kernel() {
    __shared__ int wsum[32];
    __shared__ int carry;
    int t = threadIdx.x, lane = t & 31, w = t >> 5;
    if (t == 0) { carry = 0; g_off[0] = 0; }
    __syncthreads();
    for (int base = 0; base < Nn; base += 1024) {
        int i = base + t;
        int v = (i < Nn) ? ((int)g_deg[i] + 1) : 0;
        int s = v;
#pragma unroll
        for (int o = 1; o < 32; o <<= 1) {
            int u = __shfl_up_sync(0xffffffffu, s, o);
            if (lane >= o) s += u;
        }
        if (lane == 31) wsum[w] = s;
        __syncthreads();
        if (w == 0) {
            int ws = wsum[lane];
#pragma unroll
            for (int o = 1; o < 32; o <<= 1) {
                int u = __shfl_up_sync(0xffffffffu, ws, o);
                if (lane >= o) ws += u;
            }
            wsum[lane] = ws;
        }
        __syncthreads();
        int boff = (w ? wsum[w - 1] : 0);
        if (i < Nn) g_off[i + 1] = carry + boff + s;
        __syncthreads();
        if (t == 0) carry += wsum[31];
        __syncthreads();
    }
}

__global__ void fill_kernel(const int* __restrict__ ei) {
    int i = blockIdx.x * blockDim.x + threadIdx.x;
    if (i >= TOT) return;
    int s, d;
    if (i < Ee) { s = ei[i]; d = ei[Ee + i]; }
    else        { s = i - Ee; d = s; }
    int pos = atomicAdd(&g_cur[d], 1);
    int idx = g_off[d] + pos;
    g_srcv[idx] = s;
    g_wv[idx]   = g_dinv[s] * g_dinv[d];
}

// ================= weight transpose + bf16 hi/lo split =================
// W [K, 512] fp32 -> Wt [512][K] bf16 hi/lo at offset woff

__global__ void wt_kernel(const float* __restrict__ W, int K, int woff) {
    int idx = blockIdx.x * blockDim.x + threadIdx.x;
    if (idx >= K * Hh) return;
    int k = idx / Hh, n = idx % Hh;
    float a = W[idx];
    __nv_bfloat16 h = __float2bfloat16(a);
    float rem = a - __bfloat162float(h);
    g_wt_hi[woff + n * K + k] = h;
    g_wt_lo[woff + n * K + k] = __float2bfloat16(rem);
}

// ================= warp-MMA bf16 GEMM with hi/lo compensation ===========
// C[N,512] = A[N,K] @ W[K,512]
// CTA: 128x128 tile, 256 threads = 8 warps (4m x 2n), warp tile 32x64.
// K chunked by 32. smem rows padded to 40 bf16 (80B) -> conflict-free ldmatrix.

#define BM 128
#define BN 128
#define BK 32
#define AST 40   // smem row stride in bf16 elems

__global__ void __launch_bounds__(256, 2)
mma_gemm(const float* __restrict__ Aq, int K, int woff) {
    __shared__ __align__(16) __nv_bfloat16 sA[2][BM][AST];  // [hi/lo][m][k]
    __shared__ __align__(16) __nv_bfloat16 sB[2][BN][AST];  // [hi/lo][n][k]

    const float* A = Aq ? Aq : g_x;

    const int t    = threadIdx.x;
    const int lane = t & 31;
    const int wid  = t >> 5;
    const int wm   = (wid & 3) * 32;       // warp m offset in tile
    const int wn   = (wid >> 2) * 64;      // warp n offset in tile
    const int m0   = blockIdx.y * BM;
    const int n0   = blockIdx.x * BN;

    float acc[2][8][4];
#pragma unroll
    for (int i = 0; i < 2; i++)
#pragma unroll
        for (int j = 0; j < 8; j++)
#pragma unroll
            for (int k = 0; k < 4; k++) acc[i][j][k] = 0.f;

    // global-load mapping: 2 threads per row, 16 elems each
    const int lr = t >> 1;          // 0..127 row
    const int lp = t & 1;           // half selector

    // ldmatrix base addresses (depend only on lane)
    const uint32_t aHbase = smem_u32(&sA[0][0][0]);
    const uint32_t aLbase = smem_u32(&sA[1][0][0]);
    const uint32_t bHbase = smem_u32(&sB[0][0][0]);
    const uint32_t bLbase = smem_u32(&sB[1][0][0]);
    const int arow = lane & 15, acolg = lane >> 4;            // A: rows m, 16B group = k half
    const int brow = (lane & 7) + ((lane >> 4) << 3);         // B: n row
    const int bcolg = (lane >> 3) & 1;                        // B: k half

    const int nch = K >> 5;   // chunks of 32
    for (int c = 0; c < nch; c++) {
        if (c) __syncthreads();
        const int k0 = c << 5;

        // ---- load A chunk: 128 rows x 32 fp32 -> hi/lo bf16 smem ----
        {
            int row = m0 + lr;
            const float4* src = (row < Nn) ? (const float4*)&A[(size_t)row * K + k0 + lp * 16]
                                           : nullptr;
#pragma unroll
            for (int i = 0; i < 4; i++) {
                float4 v = src ? src[i] : make_float4(0.f, 0.f, 0.f, 0.f);
                uint2 hv, lv;
                split2(v.x, v.y, hv.x, lv.x);
                split2(v.z, v.w, hv.y, lv.y);
                *(uint2*)&sA[0][lr][lp * 16 + i * 4] = hv;
                *(uint2*)&sA[1][lr][lp * 16 + i * 4] = lv;
            }
        }
        // ---- load B chunk: 128 n-rows x 32 bf16 (pre-split W^T) ----
        // 16 bf16 per thread = 2 x uint4 (bug fixed: was 1 x uint4 = 8 elems)
        {
            size_t base = (size_t)woff + (size_t)(n0 + lr) * K + k0 + lp * 16;
            uint4 bh0 = *(const uint4*)&g_wt_hi[base];
            uint4 bh1 = *(const uint4*)&g_wt_hi[base + 8];
            uint4 bl0 = *(const uint4*)&g_wt_lo[base];
            uint4 bl1 = *(const uint4*)&g_wt_lo[base + 8];
            *(uint4*)&sB[0][lr][lp * 16]     = bh0;
            *(uint4*)&sB[0][lr][lp * 16 + 8] = bh1;
            *(uint4*)&sB[1][lr][lp * 16]     = bl0;
            *(uint4*)&sB[1][lr][lp * 16 + 8] = bl1;
        }
        __syncthreads();

        // ---- compute: 2 k16-steps ----
#pragma unroll
        for (int ks = 0; ks < 2; ks++) {
            uint32_t ah[2][4], al[2][4];
#pragma unroll
            for (int mt = 0; mt < 2; mt++) {
                uint32_t off = (uint32_t)((wm + mt * 16 + arow) * AST * 2 + ks * 32 + acolg * 16);
                ldsm_x4(ah[mt], aHbase + off);
                ldsm_x4(al[mt], aLbase + off);
            }
#pragma unroll
            for (int np = 0; np < 4; np++) {
                uint32_t boff = (uint32_t)((wn + np * 16 + brow) * AST * 2 + ks * 32 + bcolg * 16);
                uint32_t bh[4], bl[4];
                ldsm_x4(bh, bHbase + boff);
                ldsm_x4(bl, bLbase + boff);
#pragma unroll
                for (int mt = 0; mt < 2; mt++) {
                    mma16816(acc[mt][np * 2 + 0], ah[mt], bh + 0);
                    mma16816(acc[mt][np * 2 + 1], ah[mt], bh + 2);
                    mma16816(acc[mt][np * 2 + 0], ah[mt], bl + 0);
                    mma16816(acc[mt][np * 2 + 1], ah[mt], bl + 2);
                    mma16816(acc[mt][np * 2 + 0], al[mt], bh + 0);
                    mma16816(acc[mt][np * 2 + 1], al[mt], bh + 2);
                }
            }
        }
    }

    // ---- epilogue: acc -> g_h ----
    const int quad = lane >> 2;
    const int qi   = lane & 3;
#pragma unroll
    for (int mt = 0; mt < 2; mt++) {
        int r0 = m0 + wm + mt * 16 + quad;
#pragma unroll
        for (int nt = 0; nt < 8; nt++) {
            int cc = n0 + wn + nt * 8 + qi * 2;
            if (r0 < Nn)
                *(float2*)&g_h[(size_t)r0 * Hh + cc] = make_float2(acc[mt][nt][0], acc[mt][nt][1]);
            if (r0 + 8 < Nn)
                *(float2*)&g_h[(size_t)(r0 + 8) * Hh + cc] = make_float2(acc[mt][nt][2], acc[mt][nt][3]);
        }
    }
}

// ======= fused CSR gather-aggregate + bias + LayerNorm + ReLU =======

__global__ void __launch_bounds__(128)
agg_kernel(const float* __restrict__ bias,
           const float* __restrict__ gamma,
           const float* __restrict__ beta) {
    const int n = blockIdx.x;
    const int t = threadIdx.x;
    const int beg = g_off[n], end = g_off[n + 1];
    const int fo = t * 4;

    float4 acc = make_float4(0.f, 0.f, 0.f, 0.f);
    for (int j = beg; j < end; j++) {
        int   s = g_srcv[j];
        float wv = g_wv[j];
        float4 v = *(const float4*)&g_h[(size_t)s * Hh + fo];
        acc.x = fmaf(wv, v.x, acc.x);
        acc.y = fmaf(wv, v.y, acc.y);
        acc.z = fmaf(wv, v.z, acc.z);
        acc.w = fmaf(wv, v.w, acc.w);
    }
    float4 b = *(const float4*)&bias[fo];
    acc.x += b.x; acc.y += b.y; acc.z += b.z; acc.w += b.w;

    float s1 = acc.x + acc.y + acc.z + acc.w;
    float s2 = acc.x * acc.x + acc.y * acc.y + acc.z * acc.z + acc.w * acc.w;
#pragma unroll
    for (int o = 16; o > 0; o >>= 1) {
        s1 += __shfl_xor_sync(0xffffffffu, s1, o);
        s2 += __shfl_xor_sync(0xffffffffu, s2, o);
    }
    __shared__ float sm1[4], sm2[4];
    if ((t & 31) == 0) { sm1[t >> 5] = s1; sm2[t >> 5] = s2; }
    __syncthreads();
    float S1 = sm1[0] + sm1[1] + sm1[2] + sm1[3];
    float S2 = sm2[0] + sm2[1] + sm2[2] + sm2[3];
    float mu  = S1 * (1.0f / Hh);
    float var = S2 * (1.0f / Hh) - mu * mu;
    float inv = rsqrtf(var + EPSL);

    float4 gm = *(const float4*)&gamma[fo];
    float4 bt = *(const float4*)&beta[fo];
    float4 y;
    y.x = fmaxf((acc.x - mu) * inv * gm.x + bt.x, 0.f);
    y.y = fmaxf((acc.y - mu) * inv * gm.y + bt.y, 0.f);
    y.z = fmaxf((acc.z - mu) * inv * gm.z + bt.z, 0.f);
    y.w = fmaxf((acc.w - mu) * inv * gm.w + bt.w, 0.f);
    *(float4*)&g_x[(size_t)n * Hh + fo] = y;
}

// ================= mean pool + output projection =================

__global__ void pool_kernel() {
    int f = threadIdx.x;
    float s = 0.f;
    for (int n = blockIdx.x; n < Nn; n += gridDim.x)
        s += g_x[(size_t)n * Hh + f];
    atomicAdd(&g_pool[f], s);
}

__global__ void out_kernel(const float* __restrict__ Wout,
                           const float* __restrict__ bout,
                           float* __restrict__ out) {
    __shared__ float sm[NOUT][256];
    int t = threadIdx.x;
    float acc[NOUT];
#pragma unroll
    for (int o = 0; o < NOUT; o++) acc[o] = 0.f;
    for (int f = t; f < Hh; f += 256) {
        float p = g_pool[f] * (1.0f / Nn);
#pragma unroll
        for (int o = 0; o < NOUT; o++)
            acc[o] = fmaf(p, Wout[f * NOUT + o], acc[o]);
    }
#pragma unroll
    for (int o = 0; o < NOUT; o++) sm[o][t] = acc[o];
    __syncthreads();
    for (int st = 128; st > 0; st >>= 1) {
        if (t < st) {
#pragma unroll
            for (int o = 0; o < NOUT; o++) sm[o][t] += sm[o][t + st];
        }
        __syncthreads();
    }
    if (t < NOUT) out[t] = sm[t][0] + bout[t];
}

// ================= launch =================

extern "C" void kernel_launch(void* const* d_in, const int* in_sizes, int n_in,
                              void* d_out, int out_size) {
    const float* x  = (const float*)d_in[0];
    const int*   ei = (const int*)d_in[1];
    const float* W1 = (const float*)d_in[2];  const float* b1 = (const float*)d_in[3];
    const float* W2 = (const float*)d_in[4];  const float* b2 = (const float*)d_in[5];
    const float* W3 = (const float*)d_in[6];  const float* b3 = (const float*)d_in[7];
    const float* W4 = (const float*)d_in[8];  const float* b4 = (const float*)d_in[9];
    const float* gm = (const float*)d_in[10]; const float* bt = (const float*)d_in[11];
    const float* Wo = (const float*)d_in[12]; const float* bo = (const float*)d_in[13];
    float* out = (float*)d_out;

    init_kernel<<<(Nn + 255) / 256, 256>>>();
    deg_kernel<<<(Ee + 255) / 256, 256>>>(ei);
    wt_kernel<<<(DIN * Hh + 255) / 256, 256>>>(W1, DIN, WOFF1);
    wt_kernel<<<(Hh * Hh + 255) / 256, 256>>>(W2, Hh, WOFF2);
    wt_kernel<<<(Hh * Hh + 255) / 256, 256>>>(W3, Hh, WOFF3);
    wt_kernel<<<(Hh * Hh + 255) / 256, 256>>>(W4, Hh, WOFF4);
    dinv_kernel<<<(Nn + 255) / 256, 256>>>();
    scan_kernel<<<1, 1024>>>();
    fill_kernel<<<(TOT + 255) / 256, 256>>>(ei);

    dim3 ggrid(Hh / BN, (Nn + BM - 1) / BM);   // (4, 157)

    mma_gemm<<<ggrid, 256>>>(x, DIN, WOFF1);
    agg_kernel<<<Nn, 128>>>(b1, gm, bt);
    mma_gemm<<<ggrid, 256>>>(nullptr, Hh, WOFF2);
    agg_kernel<<<Nn, 128>>>(b2, gm, bt);
    mma_gemm<<<ggrid, 256>>>(nullptr, Hh, WOFF3);
    agg_kernel<<<Nn, 128>>>(b3, gm, bt);
    mma_gemm<<<ggrid, 256>>>(nullptr, Hh, WOFF4);
    agg_kernel<<<Nn, 128>>>(b4, gm, bt);

    pool_kernel<<<148, 512>>>();
    out_kernel<<<1, 256>>>(Wo, bo, out);
}

// round 7
// speedup vs baseline: 2.1900x; 1.1054x over previous
#include <cuda_runtime.h>
#include <cuda_bf16.h>
#include <cstdint>

#define Nn   20000
#define NP   20096            // padded rows (157 * 128)
#define Ee   320000
#define DIN  128
#define Hh   512
#define NOUT 7
#define TOT  (Ee + Nn)
#define EPSL 1e-5f

// Wt layout: layer1 [512][128] then layers 2-4 [512][512] (hi and lo arrays)
#define WOFF1 0
#define WOFF2 65536
#define WOFF3 327680
#define WOFF4 589824
#define WTOT  851968

// ---- scratch (no allocs allowed: __device__ globals; zero-init at load) ----
__device__ float g_h[(size_t)Nn * Hh];                  // GEMM output
__device__ __nv_bfloat16 g_a_hi[(size_t)NP * Hh];       // activations hi (padded)
__device__ __nv_bfloat16 g_a_lo[(size_t)NP * Hh];       // activations lo
__device__ float g_deg[Nn];
__device__ float g_dinv[Nn];
__device__ int   g_off[Nn + 1];
__device__ int   g_cur[Nn];
__device__ int   g_srcv[TOT];
__device__ float g_wv[TOT];
__device__ float g_pool[Hh];
__device__ __nv_bfloat16 g_wt_hi[WTOT];
__device__ __nv_bfloat16 g_wt_lo[WTOT];

// ================= helpers =================

__device__ __forceinline__ uint32_t smem_u32(const void* p) {
    uint32_t a;
    asm("{ .reg .u64 t; cvta.to.shared.u64 t, %1; cvt.u32.u64 %0, t; }" : "=r"(a) : "l"(p));
    return a;
}
__device__ __forceinline__ void ldsm_x4(uint32_t* r, uint32_t addr) {
    asm volatile("ldmatrix.sync.aligned.m8n8.x4.shared.b16 {%0,%1,%2,%3}, [%4];"
                 : "=r"(r[0]), "=r"(r[1]), "=r"(r[2]), "=r"(r[3]) : "r"(addr));
}
__device__ __forceinline__ void mma16816(float* d, const uint32_t* a, const uint32_t* b) {
    asm volatile("mma.sync.aligned.m16n8k16.row.col.f32.bf16.bf16.f32 "
                 "{%0,%1,%2,%3}, {%4,%5,%6,%7}, {%8,%9}, {%0,%1,%2,%3};"
                 : "+f"(d[0]), "+f"(d[1]), "+f"(d[2]), "+f"(d[3])
                 : "r"(a[0]), "r"(a[1]), "r"(a[2]), "r"(a[3]), "r"(b[0]), "r"(b[1]));
}
__device__ __forceinline__ void cp16(uint32_t dst, const void* src) {
    asm volatile("cp.async.ca.shared.global [%0], [%1], 16;" :: "r"(dst), "l"(src));
}
__device__ __forceinline__ void cp_commit() {
    asm volatile("cp.async.commit_group;" ::: "memory");
}
template <int N> __device__ __forceinline__ void cp_wait() {
    asm volatile("cp.async.wait_group %0;" :: "n"(N) : "memory");
}

static __device__ __forceinline__ void split2(float a, float b, unsigned& h, unsigned& l) {
    __nv_bfloat162 hh = __floats2bfloat162_rn(a, b);
    float ra = a - __bfloat162float(hh.x);
    float rb = b - __bfloat162float(hh.y);
    __nv_bfloat162 ll = __floats2bfloat162_rn(ra, rb);
    h = *(unsigned*)&hh;
    l = *(unsigned*)&ll;
}

// ================= graph preprocessing =================

__global__ void init_kernel() {
    int i = blockIdx.x * blockDim.x + threadIdx.x;
    if (i < Nn) { g_deg[i] = 0.f; g_cur[i] = 0; }
    if (i < Hh) g_pool[i] = 0.f;
}

__global__ void deg_kernel(const int* __restrict__ ei) {
    int i = blockIdx.x * blockDim.x + threadIdx.x;
    if (i < Ee) atomicAdd(&g_deg[ei[Ee + i]], 1.0f);
}

// warp-shuffle based scan (+ fused dinv), 1024 threads
__global__ void scan_kernel() {
    __shared__ int wsum[32];
    __shared__ int carry;
    int t = threadIdx.x, lane = t & 31, w = t >> 5;
    if (t == 0) { carry = 0; g_off[0] = 0; }
    __syncthreads();
    for (int base = 0; base < Nn; base += 1024) {
        int i = base + t;
        int v = 0;
        if (i < Nn) {
            v = (int)g_deg[i] + 1;
            g_dinv[i] = rsqrtf((float)v);
        }
        int s = v;
#pragma unroll
        for (int o = 1; o < 32; o <<= 1) {
            int u = __shfl_up_sync(0xffffffffu, s, o);
            if (lane >= o) s += u;
        }
        if (lane == 31) wsum[w] = s;
        __syncthreads();
        if (w == 0) {
            int ws = wsum[lane];
#pragma unroll
            for (int o = 1; o < 32; o <<= 1) {
                int u = __shfl_up_sync(0xffffffffu, ws, o);
                if (lane >= o) ws += u;
            }
            wsum[lane] = ws;
        }
        __syncthreads();
        int boff = (w ? wsum[w - 1] : 0);
        if (i < Nn) g_off[i + 1] = carry + boff + s;
        __syncthreads();
        if (t == 0) carry += wsum[31];
        __syncthreads();
    }
}

__global__ void fill_kernel(const int* __restrict__ ei) {
    int i = blockIdx.x * blockDim.x + threadIdx.x;
    if (i >= TOT) return;
    int s, d;
    if (i < Ee) { s = ei[i]; d = ei[Ee + i]; }
    else        { s = i - Ee; d = s; }
    int pos = atomicAdd(&g_cur[d], 1);
    int idx = g_off[d] + pos;
    g_srcv[idx] = s;
    g_wv[idx]   = g_dinv[s] * g_dinv[d];
}

// ============== all-layer weight transpose + bf16 hi/lo split ==============

__global__ void wt_all_kernel(const float* __restrict__ W1, const float* __restrict__ W2,
                              const float* __restrict__ W3, const float* __restrict__ W4) {
    int idx = blockIdx.x * blockDim.x + threadIdx.x;
    if (idx >= WTOT) return;
    const float* W; int K, loc;
    if (idx < WOFF2)      { W = W1; K = DIN; loc = idx; }
    else if (idx < WOFF3) { W = W2; K = Hh;  loc = idx - WOFF2; }
    else if (idx < WOFF4) { W = W3; K = Hh;  loc = idx - WOFF3; }
    else                  { W = W4; K = Hh;  loc = idx - WOFF4; }
    int n = loc / K, k = loc % K;          // output index [n][k]
    float a = W[(size_t)k * Hh + n];       // source [k][n]
    __nv_bfloat16 h = __float2bfloat16(a);
    g_wt_hi[idx] = h;
    g_wt_lo[idx] = __float2bfloat16(a - __bfloat162float(h));
}

// ============== layer-1 input conversion: x fp32 -> hi/lo bf16 ==============

__global__ void cvt_kernel(const float* __restrict__ x) {
    int i = blockIdx.x * blockDim.x + threadIdx.x;
    if (i >= Nn * DIN / 2) return;
    float2 v = *(const float2*)&x[i * 2];
    unsigned h, l;
    split2(v.x, v.y, h, l);
    *(unsigned*)&g_a_hi[i * 2] = h;
    *(unsigned*)&g_a_lo[i * 2] = l;
}

// ================= warp-MMA bf16 GEMM, cp.async double-buffered ===========
// C[N,512] = A[N,K] @ W[K,512]; A pre-split hi/lo in g_a_*, W^T in g_wt_*.
// CTA: 128x128 tile, 256 threads, 8 warps (4m x 2n), warp tile 32x64, BK=32.

#define BM 128
#define BN 128
#define AST 40                  // smem row stride in bf16 (80 B)
#define STG_B 10240             // bytes per array per stage (128*80)
#define GEMM_SMEM (8 * STG_B)   // 4 arrays x 2 stages = 81920

__global__ void __launch_bounds__(256, 2)
mma_gemm(int K, int woff) {
    extern __shared__ __align__(16) char dynsmem[];
    const uint32_t sb = smem_u32(dynsmem);

    const int t    = threadIdx.x;
    const int lane = t & 31;
    const int wid  = t >> 5;
    const int wm   = (wid & 3) * 32;
    const int wn   = (wid >> 2) * 64;
    const int m0   = blockIdx.y * BM;
    const int n0   = blockIdx.x * BN;

    const __nv_bfloat16* srcp[4] = {
        g_a_hi + (size_t)m0 * K, g_a_lo + (size_t)m0 * K,
        g_wt_hi + woff + (size_t)n0 * K, g_wt_lo + woff + (size_t)n0 * K
    };

    float acc[2][8][4];
#pragma unroll
    for (int i = 0; i < 2; i++)
#pragma unroll
        for (int j = 0; j < 8; j++)
#pragma unroll
            for (int k = 0; k < 4; k++) acc[i][j][k] = 0.f;

    // cp.async issue: 2048 16B segments per stage, 8 per thread
    auto issue = [&](int c) {
        const int st = c & 1;
        const int k0 = c << 5;
#pragma unroll
        for (int i = 0; i < 8; i++) {
            int seg = t + i * 256;
            int arr = seg >> 9;
            int rem = seg & 511;
            int r   = rem >> 2;
            int sgi = rem & 3;
            uint32_t dst = sb + arr * 2 * STG_B + st * STG_B + r * 80 + sgi * 16;
            cp16(dst, srcp[arr] + (size_t)r * K + k0 + sgi * 8);
        }
        cp_commit();
    };

    // ldmatrix lane mapping
    const int arow = lane & 15, acolg = lane >> 4;
    const int brow = (lane & 7) + ((lane >> 4) << 3);
    const int bcolg = (lane >> 3) & 1;

    const int nch = K >> 5;
    issue(0);

    for (int c = 0; c < nch; c++) {
        if (c + 1 < nch) { issue(c + 1); cp_wait<1>(); }
        else             { cp_wait<0>(); }
        __syncthreads();

        const int st = c & 1;
        const uint32_t aH = sb + 0 * STG_B + st * STG_B;
        const uint32_t aL = sb + 2 * STG_B + st * STG_B;
        const uint32_t bH = sb + 4 * STG_B + st * STG_B;
        const uint32_t bL = sb + 6 * STG_B + st * STG_B;

#pragma unroll
        for (int ks = 0; ks < 2; ks++) {
            uint32_t ah[2][4], al[2][4];
#pragma unroll
            for (int mt = 0; mt < 2; mt++) {
                uint32_t off = (uint32_t)((wm + mt * 16 + arow) * 80 + ks * 32 + acolg * 16);
                ldsm_x4(ah[mt], aH + off);
                ldsm_x4(al[mt], aL + off);
            }
#pragma unroll
            for (int np = 0; np < 4; np++) {
                uint32_t boff = (uint32_t)((wn + np * 16 + brow) * 80 + ks * 32 + bcolg * 16);
                uint32_t bh[4], bl[4];
                ldsm_x4(bh, bH + boff);
                ldsm_x4(bl, bL + boff);
#pragma unroll
                for (int mt = 0; mt < 2; mt++) {
                    mma16816(acc[mt][np * 2 + 0], ah[mt], bh + 0);
                    mma16816(acc[mt][np * 2 + 1], ah[mt], bh + 2);
                    mma16816(acc[mt][np * 2 + 0], ah[mt], bl + 0);
                    mma16816(acc[mt][np * 2 + 1], ah[mt], bl + 2);
                    mma16816(acc[mt][np * 2 + 0], al[mt], bh + 0);
                    mma16816(acc[mt][np * 2 + 1], al[mt], bh + 2);
                }
            }
        }
        __syncthreads();   // stage reuse guard for next issue
    }

    // ---- epilogue: acc -> g_h (fp32) ----
    const int quad = lane >> 2;
    const int qi   = lane & 3;
#pragma unroll
    for (int mt = 0; mt < 2; mt++) {
        int r0 = m0 + wm + mt * 16 + quad;
#pragma unroll
        for (int nt = 0; nt < 8; nt++) {
            int cc = n0 + wn + nt * 8 + qi * 2;
            if (r0 < Nn)
                *(float2*)&g_h[(size_t)r0 * Hh + cc] = make_float2(acc[mt][nt][0], acc[mt][nt][1]);
            if (r0 + 8 < Nn)
                *(float2*)&g_h[(size_t)(r0 + 8) * Hh + cc] = make_float2(acc[mt][nt][2], acc[mt][nt][3]);
        }
    }
}

// ======= fused CSR gather-aggregate + bias + LayerNorm + ReLU =======
// output written as pre-split hi/lo bf16 for the next GEMM / pool

__global__ void __launch_bounds__(128)
agg_kernel(const float* __restrict__ bias,
           const float* __restrict__ gamma,
           const float* __restrict__ beta) {
    const int n = blockIdx.x;
    const int t = threadIdx.x;
    const int beg = g_off[n], end = g_off[n + 1];
    const int fo = t * 4;

    float4 acc = make_float4(0.f, 0.f, 0.f, 0.f);
#pragma unroll 2
    for (int j = beg; j < end; j++) {
        int   s = g_srcv[j];
        float wv = g_wv[j];
        float4 v = *(const float4*)&g_h[(size_t)s * Hh + fo];
        acc.x = fmaf(wv, v.x, acc.x);
        acc.y = fmaf(wv, v.y, acc.y);
        acc.z = fmaf(wv, v.z, acc.z);
        acc.w = fmaf(wv, v.w, acc.w);
    }
    float4 b = *(const float4*)&bias[fo];
    acc.x += b.x; acc.y += b.y; acc.z += b.z; acc.w += b.w;

    float s1 = acc.x + acc.y + acc.z + acc.w;
    float s2 = acc.x * acc.x + acc.y * acc.y + acc.z * acc.z + acc.w * acc.w;
#pragma unroll
    for (int o = 16; o > 0; o >>= 1) {
        s1 += __shfl_xor_sync(0xffffffffu, s1, o);
        s2 += __shfl_xor_sync(0xffffffffu, s2, o);
    }
    __shared__ float sm1[4], sm2[4];
    if ((t & 31) == 0) { sm1[t >> 5] = s1; sm2[t >> 5] = s2; }
    __syncthreads();
    float S1 = sm1[0] + sm1[1] + sm1[2] + sm1[3];
    float S2 = sm2[0] + sm2[1] + sm2[2] + sm2[3];
    float mu  = S1 * (1.0f / Hh);
    float var = S2 * (1.0f / Hh) - mu * mu;
    float inv = rsqrtf(var + EPSL);

    float4 gm = *(const float4*)&gamma[fo];
    float4 bt = *(const float4*)&beta[fo];
    float4 y;
    y.x = fmaxf((acc.x - mu) * inv * gm.x + bt.x, 0.f);
    y.y = fmaxf((acc.y - mu) * inv * gm.y + bt.y, 0.f);
    y.z = fmaxf((acc.z - mu) * inv * gm.z + bt.z, 0.f);
    y.w = fmaxf((acc.w - mu) * inv * gm.w + bt.w, 0.f);

    uint2 hv, lv;
    split2(y.x, y.y, hv.x, lv.x);
    split2(y.z, y.w, hv.y, lv.y);
    *(uint2*)&g_a_hi[(size_t)n * Hh + fo] = hv;
    *(uint2*)&g_a_lo[(size_t)n * Hh + fo] = lv;
}

// ================= mean pool + output projection =================

__global__ void pool_kernel() {
    int f = threadIdx.x;
    float s = 0.f;
    for (int n = blockIdx.x; n < Nn; n += gridDim.x) {
        size_t idx = (size_t)n * Hh + f;
        s += __bfloat162float(g_a_hi[idx]) + __bfloat162float(g_a_lo[idx]);
    }
    atomicAdd(&g_pool[f], s);
}

__global__ void out_kernel(const float* __restrict__ Wout,
                           const float* __restrict__ bout,
                           float* __restrict__ out) {
    __shared__ float sm[NOUT][256];
    int t = threadIdx.x;
    float acc[NOUT];
#pragma unroll
    for (int o = 0; o < NOUT; o++) acc[o] = 0.f;
    for (int f = t; f < Hh; f += 256) {
        float p = g_pool[f] * (1.0f / Nn);
#pragma unroll
        for (int o = 0; o < NOUT; o++)
            acc[o] = fmaf(p, Wout[f * NOUT + o], acc[o]);
    }
#pragma unroll
    for (int o = 0; o < NOUT; o++) sm[o][t] = acc[o];
    __syncthreads();
    for (int st = 128; st > 0; st >>= 1) {
        if (t < st) {
#pragma unroll
            for (int o = 0; o < NOUT; o++) sm[o][t] += sm[o][t + st];
        }
        __syncthreads();
    }
    if (t < NOUT) out[t] = sm[t][0] + bout[t];
}

// ================= launch =================

extern "C" void kernel_launch(void* const* d_in, const int* in_sizes, int n_in,
                              void* d_out, int out_size) {
    const float* x  = (const float*)d_in[0];
    const int*   ei = (const int*)d_in[1];
    const float* W1 = (const float*)d_in[2];  const float* b1 = (const float*)d_in[3];
    const float* W2 = (const float*)d_in[4];  const float* b2 = (const float*)d_in[5];
    const float* W3 = (const float*)d_in[6];  const float* b3 = (const float*)d_in[7];
    const float* W4 = (const float*)d_in[8];  const float* b4 = (const float*)d_in[9];
    const float* gm = (const float*)d_in[10]; const float* bt = (const float*)d_in[11];
    const float* Wo = (const float*)d_in[12]; const float* bo = (const float*)d_in[13];
    float* out = (float*)d_out;

    cudaFuncSetAttribute(mma_gemm, cudaFuncAttributeMaxDynamicSharedMemorySize, GEMM_SMEM);

    init_kernel<<<(Nn + 255) / 256, 256>>>();
    deg_kernel<<<(Ee + 255) / 256, 256>>>(ei);
    wt_all_kernel<<<(WTOT + 255) / 256, 256>>>(W1, W2, W3, W4);
    cvt_kernel<<<(Nn * DIN / 2 + 255) / 256, 256>>>(x);
    scan_kernel<<<1, 1024>>>();
    fill_kernel<<<(TOT + 255) / 256, 256>>>(ei);

    dim3 ggrid(Hh / BN, NP / BM);   // (4, 157)

    mma_gemm<<<ggrid, 256, GEMM_SMEM>>>(DIN, WOFF1);
    agg_kernel<<<Nn, 128>>>(b1, gm, bt);
    mma_gemm<<<ggrid, 256, GEMM_SMEM>>>(Hh, WOFF2);
    agg_kernel<<<Nn, 128>>>(b2, gm, bt);
    mma_gemm<<<ggrid, 256, GEMM_SMEM>>>(Hh, WOFF3);
    agg_kernel<<<Nn, 128>>>(b3, gm, bt);
    mma_gemm<<<ggrid, 256, GEMM_SMEM>>>(Hh, WOFF4);
    agg_kernel<<<Nn, 128>>>(b4, gm, bt);

    pool_kernel<<<148, 512>>>();
    out_kernel<<<1, 256>>>(Wo, bo, out);
}